// round 2
// baseline (speedup 1.0000x reference)
#include <cuda_runtime.h>
#include <math.h>
#include <math_constants.h>

#define BS 16
#define Q 900
#define NC 92
#define T 100
#define NT (BS * T)   // 1600
#define NK 8          // columns per thread in LSA (128 threads * 8 >= 901)

// Transposed per-batch cost slice: ct[b][t][q] = C[b, q, b*T + t]
__device__ float g_ct[BS][T][Q];

// ---------------------------------------------------------------------------
// Kernel 1: cost matrix. One block per (b,q). Softmax probs hoisted to shared
// (92 expf per block instead of 1600).
// ---------------------------------------------------------------------------
__global__ void __launch_bounds__(256) cost_kernel(
    const float* __restrict__ logits,   // [BS*Q, NC]
    const float* __restrict__ pboxes,   // [BS*Q, 4]  cxcywh
    const int*   __restrict__ tgt_ids,  // [NT]
    const float* __restrict__ tbox,     // [NT, 4]    xyxy
    float* __restrict__ C)              // [BS*Q, NT]
{
    const int bq  = blockIdx.x;
    const int b   = bq / Q;
    const int q   = bq - b * Q;
    const int tid = threadIdx.x;

    __shared__ float sl[NC];
    __shared__ float sp[NC];
    __shared__ float smax, ssum;

    const float* L = logits + (size_t)bq * NC;
    if (tid < NC) sl[tid] = L[tid];
    __syncthreads();

    if (tid < 32) {
        float m = -CUDART_INF_F;
        for (int c = tid; c < NC; c += 32) m = fmaxf(m, sl[c]);
        #pragma unroll
        for (int o = 16; o; o >>= 1) m = fmaxf(m, __shfl_xor_sync(0xffffffffu, m, o));
        float s = 0.f;
        for (int c = tid; c < NC; c += 32) s += expf(sl[c] - m);
        #pragma unroll
        for (int o = 16; o; o >>= 1) s += __shfl_xor_sync(0xffffffffu, s, o);
        if (tid == 0) { smax = m; ssum = s; }
    }
    __syncthreads();

    if (tid < NC) sp[tid] = expf(sl[tid] - smax) / ssum;
    __syncthreads();

    const float cx = pboxes[bq * 4 + 0];
    const float cy = pboxes[bq * 4 + 1];
    const float w  = pboxes[bq * 4 + 2];
    const float h  = pboxes[bq * 4 + 3];
    const float px0 = cx - w * 0.5f, py0 = cy - h * 0.5f;
    const float px1 = cx + w * 0.5f, py1 = cy + h * 0.5f;
    const float area_a = (px1 - px0) * (py1 - py0);

    float* Crow = C + (size_t)bq * NT;
    const float4* tb4 = reinterpret_cast<const float4*>(tbox);

    for (int j = tid; j < NT; j += 256) {
        const int id = __ldg(tgt_ids + j);
        const float prob = sp[id];

        const float4 tb = __ldg(tb4 + j);
        const float tx0 = tb.x, ty0 = tb.y, tx1 = tb.z, ty1 = tb.w;

        const float tcx = (tx0 + tx1) * 0.5f, tcy = (ty0 + ty1) * 0.5f;
        const float tw  = tx1 - tx0,          th  = ty1 - ty0;

        const float cb = fabsf(cx - tcx) + fabsf(cy - tcy) + fabsf(w - tw) + fabsf(h - th);

        const float area_b = tw * th;
        const float ltx = fmaxf(px0, tx0), lty = fmaxf(py0, ty0);
        const float rbx = fminf(px1, tx1), rby = fminf(py1, ty1);
        const float iw = fmaxf(rbx - ltx, 0.f), ih = fmaxf(rby - lty, 0.f);
        const float inter = iw * ih;
        const float uni = area_a + area_b - inter;
        const float iou = inter / uni;
        const float lcx = fminf(px0, tx0), lcy = fminf(py0, ty0);
        const float rcx = fmaxf(px1, tx1), rcy = fmaxf(py1, ty1);
        const float cw = fmaxf(rcx - lcx, 0.f), ch = fmaxf(rcy - lcy, 0.f);
        const float ac = cw * ch;
        const float giou = iou - (ac - uni) / ac;

        float cost = 5.0f * cb + (-prob);
        cost = cost + 2.0f * (-giou);

        Crow[j] = cost;

        const int tl = j - b * T;
        if (tl >= 0 && tl < T) g_ct[b][tl][q] = cost;
    }
}

// ---------------------------------------------------------------------------
// Kernel 2: Jonker-Volgenant LSA, one block (128 threads) per batch.
// 2 __syncthreads per inner iteration: warp0 pre-reads next (i0, u[i0]) for
// column j1 before the dual update (safe: j1's row is not in the update set).
// ---------------------------------------------------------------------------
__device__ __forceinline__ void amin_combine(float& v, int& i, float v2, int i2) {
    if (v2 < v || (v2 == v && i2 < i)) { v = v2; i = i2; }
}

__global__ void __launch_bounds__(128) lsa_kernel(
    float* __restrict__ rows_out,   // [BS*T]
    float* __restrict__ cols_out)   // [BS*T]
{
    const int b    = blockIdx.x;
    const int tid  = threadIdx.x;
    const int lane = tid & 31;
    const int wid  = tid >> 5;

    __shared__ float u[T + 1];
    __shared__ int   p[Q + 1];
    __shared__ int   sway[Q + 1];
    __shared__ float red_v[4];
    __shared__ int   red_i[4];
    __shared__ float sdelta, snext_u;
    __shared__ int   sj1, snext_i0, srun;
    __shared__ int   ans[T];

    for (int k = tid; k <= T; k += 128) u[k] = 0.f;
    for (int k = tid; k <= Q; k += 128) p[k] = 0;

    float v[NK];
    float minv[NK];
    bool  used[NK];
    #pragma unroll
    for (int k = 0; k < NK; ++k) v[k] = 0.f;
    __syncthreads();

    for (int i = 1; i <= T; ++i) {
        #pragma unroll
        for (int k = 0; k < NK; ++k) { minv[k] = CUDART_INF_F; used[k] = false; }
        if (tid == 0) p[0] = i;

        int   j0   = 0;
        int   i0   = i;
        float u_i0 = u[i];          // consistent: row barrier precedes

        while (true) {
            const float* crow = &g_ct[b][i0 - 1][0];

            float bestv = CUDART_INF_F;
            int   besti = 0x7FFFFFF0;
            #pragma unroll
            for (int k = 0; k < NK; ++k) {
                const int jc = tid + 128 * k;
                if (jc == j0) used[k] = true;
                if (jc >= 1 && jc <= Q && !used[k]) {
                    const float cur = __ldg(crow + (jc - 1)) - u_i0 - v[k];
                    if (cur < minv[k]) { minv[k] = cur; sway[jc] = j0; }
                    if (minv[k] < bestv) { bestv = minv[k]; besti = jc; }
                }
            }

            // intra-warp argmin (first-index tiebreak)
            #pragma unroll
            for (int o = 16; o; o >>= 1) {
                const float v2 = __shfl_xor_sync(0xffffffffu, bestv, o);
                const int   i2 = __shfl_xor_sync(0xffffffffu, besti, o);
                amin_combine(bestv, besti, v2, i2);
            }
            if (lane == 0) { red_v[wid] = bestv; red_i[wid] = besti; }
            __syncthreads();                                        // (1)

            if (tid < 32) {
                float vv = (lane < 4) ? red_v[lane] : CUDART_INF_F;
                int   ii = (lane < 4) ? red_i[lane] : 0x7FFFFFF0;
                #pragma unroll
                for (int o = 2; o; o >>= 1) {
                    const float v2 = __shfl_xor_sync(0xffffffffu, vv, o);
                    const int   i2 = __shfl_xor_sync(0xffffffffu, ii, o);
                    amin_combine(vv, ii, v2, i2);
                }
                if (lane == 0) {
                    sdelta = vv;
                    sj1 = ii;
                    const int nx = p[ii];     // j1's row: NOT in this iter's update set
                    snext_i0 = nx;
                    snext_u  = u[nx];
                    srun     = (nx != 0);
                }
            }
            __syncthreads();                                        // (2)

            const float delta = sdelta;
            const int   j1    = sj1;
            const int   run   = srun;
            const int   ni0   = snext_i0;
            const float nu    = snext_u;

            #pragma unroll
            for (int k = 0; k < NK; ++k) {
                const int jc = tid + 128 * k;
                if (jc <= Q) {
                    if (used[k]) { u[p[jc]] += delta; v[k] -= delta; }
                    else if (jc >= 1) minv[k] -= delta;
                }
            }

            j0 = j1; i0 = ni0; u_i0 = nu;
            if (!run) break;
        }

        // augment (serial, short)
        if (tid == 0) {
            int j0a = j0;
            while (j0a) {
                const int j1a = sway[j0a];
                p[j0a] = p[j1a];
                j0a = j1a;
            }
        }
        __syncthreads();   // row barrier: orders augment + final u updates
    }

    // extract: ans[t] = pred column for target t
    for (int jc = tid + 1; jc <= Q; jc += 128) {
        const int r = p[jc];
        if (r > 0) ans[r - 1] = jc - 1;
    }
    __syncthreads();

    if (tid < T) {
        const int a = ans[tid];
        int rank = 0;
        #pragma unroll 4
        for (int t = 0; t < T; ++t) rank += (ans[t] < a);
        rows_out[b * T + rank] = (float)a;
        cols_out[b * T + rank] = (float)tid;
    }
}

// ---------------------------------------------------------------------------
extern "C" void kernel_launch(void* const* d_in, const int* in_sizes, int n_in,
                              void* d_out, int out_size) {
    const float* logits = (const float*)d_in[0];
    const float* pboxes = (const float*)d_in[1];
    const int*   ids    = (const int*)d_in[2];
    const float* tbox   = (const float*)d_in[3];
    float* out = (float*)d_out;

    const long long CN = (long long)BS * Q * NT;   // 23,040,000

    cost_kernel<<<BS * Q, 256>>>(logits, pboxes, ids, tbox, out);

    if ((long long)out_size >= CN + 2LL * BS * T) {
        lsa_kernel<<<BS, 128>>>(out + CN, out + CN + (long long)BS * T);
    }
}

// round 3
// speedup vs baseline: 1.0129x; 1.0129x over previous
#include <cuda_runtime.h>
#include <math.h>
#include <math_constants.h>

#define BS 16
#define Q 900
#define NC 92
#define T 100
#define NT (BS * T)   // 1600
#define NK 8          // columns per thread in LSA (128 threads * 8 >= 901)

// Transposed per-batch cost slice: ct[b][t][q] = C[b, q, b*T + t]
__device__ float g_ct[BS][T][Q];

// ---------------------------------------------------------------------------
// Kernel 1: cost matrix. One block per (b,q). Softmax probs hoisted to shared
// (92 expf per block instead of 1600).
// ---------------------------------------------------------------------------
__global__ void __launch_bounds__(256) cost_kernel(
    const float* __restrict__ logits,   // [BS*Q, NC]
    const float* __restrict__ pboxes,   // [BS*Q, 4]  cxcywh
    const int*   __restrict__ tgt_ids,  // [NT]
    const float* __restrict__ tbox,     // [NT, 4]    xyxy
    float* __restrict__ C)              // [BS*Q, NT]
{
    const int bq  = blockIdx.x;
    const int b   = bq / Q;
    const int q   = bq - b * Q;
    const int tid = threadIdx.x;

    __shared__ float sl[NC];
    __shared__ float sp[NC];
    __shared__ float smax, ssum;

    const float* L = logits + (size_t)bq * NC;
    if (tid < NC) sl[tid] = L[tid];
    __syncthreads();

    if (tid < 32) {
        float m = -CUDART_INF_F;
        for (int c = tid; c < NC; c += 32) m = fmaxf(m, sl[c]);
        #pragma unroll
        for (int o = 16; o; o >>= 1) m = fmaxf(m, __shfl_xor_sync(0xffffffffu, m, o));
        float s = 0.f;
        for (int c = tid; c < NC; c += 32) s += expf(sl[c] - m);
        #pragma unroll
        for (int o = 16; o; o >>= 1) s += __shfl_xor_sync(0xffffffffu, s, o);
        if (tid == 0) { smax = m; ssum = s; }
    }
    __syncthreads();

    if (tid < NC) sp[tid] = expf(sl[tid] - smax) / ssum;
    __syncthreads();

    const float cx = pboxes[bq * 4 + 0];
    const float cy = pboxes[bq * 4 + 1];
    const float w  = pboxes[bq * 4 + 2];
    const float h  = pboxes[bq * 4 + 3];
    const float px0 = cx - w * 0.5f, py0 = cy - h * 0.5f;
    const float px1 = cx + w * 0.5f, py1 = cy + h * 0.5f;
    const float area_a = (px1 - px0) * (py1 - py0);

    float* Crow = C + (size_t)bq * NT;
    const float4* tb4 = reinterpret_cast<const float4*>(tbox);

    for (int j = tid; j < NT; j += 256) {
        const int id = __ldg(tgt_ids + j);
        const float prob = sp[id];

        const float4 tb = __ldg(tb4 + j);
        const float tx0 = tb.x, ty0 = tb.y, tx1 = tb.z, ty1 = tb.w;

        const float tcx = (tx0 + tx1) * 0.5f, tcy = (ty0 + ty1) * 0.5f;
        const float tw  = tx1 - tx0,          th  = ty1 - ty0;

        const float cb = fabsf(cx - tcx) + fabsf(cy - tcy) + fabsf(w - tw) + fabsf(h - th);

        const float area_b = tw * th;
        const float ltx = fmaxf(px0, tx0), lty = fmaxf(py0, ty0);
        const float rbx = fminf(px1, tx1), rby = fminf(py1, ty1);
        const float iw = fmaxf(rbx - ltx, 0.f), ih = fmaxf(rby - lty, 0.f);
        const float inter = iw * ih;
        const float uni = area_a + area_b - inter;
        const float iou = inter / uni;
        const float lcx = fminf(px0, tx0), lcy = fminf(py0, ty0);
        const float rcx = fmaxf(px1, tx1), rcy = fmaxf(py1, ty1);
        const float cw = fmaxf(rcx - lcx, 0.f), ch = fmaxf(rcy - lcy, 0.f);
        const float ac = cw * ch;
        const float giou = iou - (ac - uni) / ac;

        float cost = 5.0f * cb + (-prob);
        cost = cost + 2.0f * (-giou);

        Crow[j] = cost;

        const int tl = j - b * T;
        if (tl >= 0 && tl < T) g_ct[b][tl][q] = cost;
    }
}

// ---------------------------------------------------------------------------
// Kernel 2: Jonker-Volgenant LSA, one block (128 threads) per batch.
// 2 __syncthreads per inner iteration: warp0 pre-reads next (i0, u[i0]) for
// column j1 before the dual update (safe: j1's row is not in the update set).
// ---------------------------------------------------------------------------
__device__ __forceinline__ void amin_combine(float& v, int& i, float v2, int i2) {
    if (v2 < v || (v2 == v && i2 < i)) { v = v2; i = i2; }
}

__global__ void __launch_bounds__(128) lsa_kernel(
    float* __restrict__ rows_out,   // [BS*T]
    float* __restrict__ cols_out)   // [BS*T]
{
    const int b    = blockIdx.x;
    const int tid  = threadIdx.x;
    const int lane = tid & 31;
    const int wid  = tid >> 5;

    __shared__ float u[T + 1];
    __shared__ int   p[Q + 1];
    __shared__ int   sway[Q + 1];
    __shared__ float red_v[4];
    __shared__ int   red_i[4];
    __shared__ float sdelta, snext_u;
    __shared__ int   sj1, snext_i0, srun;
    __shared__ int   ans[T];

    for (int k = tid; k <= T; k += 128) u[k] = 0.f;
    for (int k = tid; k <= Q; k += 128) p[k] = 0;

    float v[NK];
    float minv[NK];
    bool  used[NK];
    #pragma unroll
    for (int k = 0; k < NK; ++k) v[k] = 0.f;
    __syncthreads();

    for (int i = 1; i <= T; ++i) {
        #pragma unroll
        for (int k = 0; k < NK; ++k) { minv[k] = CUDART_INF_F; used[k] = false; }
        if (tid == 0) p[0] = i;

        int   j0   = 0;
        int   i0   = i;
        float u_i0 = u[i];          // consistent: row barrier precedes

        while (true) {
            const float* crow = &g_ct[b][i0 - 1][0];

            float bestv = CUDART_INF_F;
            int   besti = 0x7FFFFFF0;
            #pragma unroll
            for (int k = 0; k < NK; ++k) {
                const int jc = tid + 128 * k;
                if (jc == j0) used[k] = true;
                if (jc >= 1 && jc <= Q && !used[k]) {
                    const float cur = __ldg(crow + (jc - 1)) - u_i0 - v[k];
                    if (cur < minv[k]) { minv[k] = cur; sway[jc] = j0; }
                    if (minv[k] < bestv) { bestv = minv[k]; besti = jc; }
                }
            }

            // intra-warp argmin (first-index tiebreak)
            #pragma unroll
            for (int o = 16; o; o >>= 1) {
                const float v2 = __shfl_xor_sync(0xffffffffu, bestv, o);
                const int   i2 = __shfl_xor_sync(0xffffffffu, besti, o);
                amin_combine(bestv, besti, v2, i2);
            }
            if (lane == 0) { red_v[wid] = bestv; red_i[wid] = besti; }
            __syncthreads();                                        // (1)

            if (tid < 32) {
                float vv = (lane < 4) ? red_v[lane] : CUDART_INF_F;
                int   ii = (lane < 4) ? red_i[lane] : 0x7FFFFFF0;
                #pragma unroll
                for (int o = 2; o; o >>= 1) {
                    const float v2 = __shfl_xor_sync(0xffffffffu, vv, o);
                    const int   i2 = __shfl_xor_sync(0xffffffffu, ii, o);
                    amin_combine(vv, ii, v2, i2);
                }
                if (lane == 0) {
                    sdelta = vv;
                    sj1 = ii;
                    const int nx = p[ii];     // j1's row: NOT in this iter's update set
                    snext_i0 = nx;
                    snext_u  = u[nx];
                    srun     = (nx != 0);
                }
            }
            __syncthreads();                                        // (2)

            const float delta = sdelta;
            const int   j1    = sj1;
            const int   run   = srun;
            const int   ni0   = snext_i0;
            const float nu    = snext_u;

            #pragma unroll
            for (int k = 0; k < NK; ++k) {
                const int jc = tid + 128 * k;
                if (jc <= Q) {
                    if (used[k]) { u[p[jc]] += delta; v[k] -= delta; }
                    else if (jc >= 1) minv[k] -= delta;
                }
            }

            j0 = j1; i0 = ni0; u_i0 = nu;
            if (!run) break;
        }

        // augment (serial, short)
        if (tid == 0) {
            int j0a = j0;
            while (j0a) {
                const int j1a = sway[j0a];
                p[j0a] = p[j1a];
                j0a = j1a;
            }
        }
        __syncthreads();   // row barrier: orders augment + final u updates
    }

    // extract: ans[t] = pred column for target t
    for (int jc = tid + 1; jc <= Q; jc += 128) {
        const int r = p[jc];
        if (r > 0) ans[r - 1] = jc - 1;
    }
    __syncthreads();

    if (tid < T) {
        const int a = ans[tid];
        int rank = 0;
        #pragma unroll 4
        for (int t = 0; t < T; ++t) rank += (ans[t] < a);
        rows_out[b * T + rank] = (float)a;
        cols_out[b * T + rank] = (float)tid;
    }
}

// ---------------------------------------------------------------------------
extern "C" void kernel_launch(void* const* d_in, const int* in_sizes, int n_in,
                              void* d_out, int out_size) {
    const float* logits = (const float*)d_in[0];
    const float* pboxes = (const float*)d_in[1];
    const int*   ids    = (const int*)d_in[2];
    const float* tbox   = (const float*)d_in[3];
    float* out = (float*)d_out;

    const long long CN = (long long)BS * Q * NT;   // 23,040,000

    cost_kernel<<<BS * Q, 256>>>(logits, pboxes, ids, tbox, out);

    if ((long long)out_size >= CN + 2LL * BS * T) {
        lsa_kernel<<<BS, 128>>>(out + CN, out + CN + (long long)BS * T);
    }
}